// round 14
// baseline (speedup 1.0000x reference)
#include <cuda_runtime.h>
#include <math.h>
#include <stddef.h>
#include <stdint.h>

// Problem constants: Dur=32, Dim=256, T=528
#define TT 528
#define NQB 24          // q-partial blocks for m (22 q each)
#define QPB 22

// Scratch (device globals: allocation-free)
// parts: 0,1 = ihalf{0,1} of taps 0..15 (or full K if K<=16); 2,3 = taps 16+
__device__ float g_ypart[4][256 * TT];
__device__ float g_mpart[NQB][4][TT];
__device__ float g_ipbdot[NQB][4];
__device__ float g_sp[32][8][2];        // per (branch, o-group) partial {s, s2}
__device__ float g_pdot2[128][4];       // per (branch*4+tg, w) partial u.m dot
__device__ int   g_cnt;                 // kB completion counter (self-reset)

// k_conv shared: xs1 transposed x + NBUF weight buffers (transposed, pad-free)
#define XR 34
#define XS1_FLOATS (128 * XR)           // 4352 floats = 17408 B
#define WS_BYTES 49152                  // max: NBUF=3 x 4096 floats (C4=4)
#define SMEM_BYTES (XS1_FLOATS * 4 + WS_BYTES)   // 66560 B -> 3 blocks/SM

typedef unsigned long long ull;

__device__ __forceinline__ uint32_t smem_u32(const void* p) {
    return (uint32_t)__cvta_generic_to_shared(p);
}
__device__ __forceinline__ ull pk2(float lo, float hi) {
    ull r;
    asm("mov.b64 %0, {%1, %2};" : "=l"(r) : "f"(lo), "f"(hi));
    return r;
}
__device__ __forceinline__ void upk2(float& lo, float& hi, ull v) {
    asm("mov.b64 {%0, %1}, %2;" : "=f"(lo), "=f"(hi) : "l"(v));
}
__device__ __forceinline__ void fma2(ull& d, ull a, ull b) {
    asm("fma.rn.f32x2 %0, %1, %2, %0;" : "+l"(d) : "l"(a), "l"(b));
}
// (hi(a), lo(b)) -- the odd-tap pair, built from the even-pair registers
__device__ __forceinline__ ull xmk(ull a, ull b) {
    float al, ah, bl, bh;
    upk2(al, ah, a);
    upk2(bl, bh, b);
    return pk2(ah, bl);
}

// ---------------------------------------------------------------------------
// Conv sub-branch: taps [KOFF, KOFF+K) of a branch with output length L.
// K <= 16. Single transposed x copy; odd-tap pairs via register repack.
// Weights in transposed SMEM layout ws[c][row] (16B/lane, conflict-free),
// cp.async pipelined NBUF deep.
// ---------------------------------------------------------------------------
template<int K, int L, int KOFF>
__device__ __forceinline__ void conv_branch(
    const float* __restrict__ wB,
    const float* __restrict__ xs1,
    float* __restrict__ ws,
    int otile, int ihalf, int tid,
    float* __restrict__ yout)
{
    constexpr int C4 = (K + 3) / 4;                  // 1..4 chunks of 4 taps
    constexpr int NBUF = (C4 == 4) ? 3 : ((C4 == 3) ? 4 : ((C4 == 2) ? 6 : 8));
    constexpr int BUF = C4 * 1024;                   // floats per buffer
    constexpr int L2 = L / 2;
    // number of xe pairs needed (covers all even taps + xo construction)
    constexpr int NXE = (L2 == 0) ? 0
                      : ((K == 1) ? L2
                      : ((K % 2 == 0) ? (L2 + K / 2) : (L2 + (K - 1) / 2)));

    const int g = tid & 7;
    const int o = otile * 32 + (tid >> 3);

    ull acc2[L2 > 0 ? L2 : 1];
#pragma unroll
    for (int t = 0; t < L2; t++) acc2[t] = 0ull;
    float accT = 0.0f;

    auto stage = [&](int ii) {
        const int ibase = ihalf * 128 + ii * 8;
        const uint32_t wsb = smem_u32(ws + (ii % NBUF) * BUF);
#pragma unroll
        for (int k = 0; k < C4; k++) {
            int idx = tid + 256 * k;
            int r = idx / C4;
            int c = idx - r * C4;
            const float* src = wB + (size_t)(otile * 32 + (r >> 3)) * 8192
                                  + (size_t)(ibase + (r & 7)) * 32 + KOFF + c * 4;
            asm volatile("cp.async.cg.shared.global [%0], [%1], 16;"
                         :: "r"(wsb + (uint32_t)(c * 4096 + r * 16)), "l"(src));
        }
        asm volatile("cp.async.commit_group;");
    };

#pragma unroll
    for (int p = 0; p < NBUF - 1; p++) stage(p);

    for (int ii = 0; ii < 16; ++ii) {
        if (ii <= 16 - NBUF + 1) {
            asm volatile("cp.async.wait_group %0;" :: "n"(NBUF - 2));
        } else {
            asm volatile("cp.async.wait_group 0;");
        }
        __syncthreads();
        if (ii + NBUF - 1 < 16) stage(ii + NBUF - 1);

        const int il = ii * 8 + g;
        const float* x1r = xs1 + il * XR + KOFF;

        // even-pair register cache of the x window
        ull xe[NXE > 0 ? NXE : 1];
#pragma unroll
        for (int m = 0; m < NXE; m++)
            xe[m] = *reinterpret_cast<const ull*>(x1r + 2 * m);

        const float* wbase = ws + (ii % NBUF) * BUF;
#pragma unroll
        for (int c = 0; c < C4; c++) {
            float4 w4 = *reinterpret_cast<const float4*>(wbase + c * 1024 + tid * 4);
            ull ww0 = pk2(w4.x, w4.x);
            ull ww1 = pk2(w4.y, w4.y);
            ull ww2 = pk2(w4.z, w4.z);
            ull ww3 = pk2(w4.w, w4.w);
#pragma unroll
            for (int tp = 0; tp < L2; tp++) {
                const int m0 = tp + 2 * c;
                if (4 * c + 0 < K) fma2(acc2[tp], xe[m0], ww0);
                if (4 * c + 1 < K) fma2(acc2[tp], xmk(xe[m0], xe[m0 + 1]), ww1);
                if (4 * c + 2 < K) fma2(acc2[tp], xe[m0 + 1], ww2);
                if (4 * c + 3 < K) fma2(acc2[tp], xmk(xe[m0 + 1], xe[m0 + 2]), ww3);
            }
            if constexpr (L & 1) {   // scalar tail row t = L-1
                if (4 * c + 0 < K) accT = fmaf(x1r[L - 1 + 4 * c + 0], w4.x, accT);
                if (4 * c + 1 < K) accT = fmaf(x1r[L - 1 + 4 * c + 1], w4.y, accT);
                if (4 * c + 2 < K) accT = fmaf(x1r[L - 1 + 4 * c + 2], w4.z, accT);
                if (4 * c + 3 < K) accT = fmaf(x1r[L - 1 + 4 * c + 3], w4.w, accT);
            }
        }
        __syncwarp();
    }

    // unpack, reduce over the 8 i-lanes via warp shuffles, store
#pragma unroll
    for (int tp = 0; tp < L2; tp++) {
        float a0, a1;
        upk2(a0, a1, acc2[tp]);
#pragma unroll
        for (int m = 1; m <= 4; m <<= 1) {
            a0 += __shfl_xor_sync(0xffffffffu, a0, m);
            a1 += __shfl_xor_sync(0xffffffffu, a1, m);
        }
        if (g == 0) {
            yout[(2 * tp) * 256 + o] = a0;
            yout[(2 * tp + 1) * 256 + o] = a1;
        }
    }
    if constexpr (L & 1) {
#pragma unroll
        for (int m = 1; m <= 4; m <<= 1)
            accT += __shfl_xor_sync(0xffffffffu, accT, m);
        if (g == 0) yout[(L - 1) * 256 + o] = accT;
    }
}

#define TOFF_OF(B) ((B) * 32 - ((B) * ((B) - 1)) / 2)

template<int B>
__device__ __forceinline__ void dispatch_full(
    int b, const float* __restrict__ cw, const float* __restrict__ xs1,
    float* __restrict__ ws, int otile, int ihalf, int tid)
{
    if (b == B) {
        conv_branch<B + 1, 32 - B, 0>(cw + (size_t)B * (256 * 256 * 32),
                                      xs1, ws, otile, ihalf, tid,
                                      &g_ypart[ihalf][TOFF_OF(B) * 256]);
    } else if constexpr (B < 15) {
        dispatch_full<B + 1>(b, cw, xs1, ws, otile, ihalf, tid);
    }
}

template<int B>
__device__ __forceinline__ void dispatch_k1(
    int b, const float* __restrict__ cw, const float* __restrict__ xs1,
    float* __restrict__ ws, int otile, int ihalf, int tid)
{
    if (b == B) {
        conv_branch<16, 32 - B, 0>(cw + (size_t)B * (256 * 256 * 32),
                                   xs1, ws, otile, ihalf, tid,
                                   &g_ypart[ihalf][TOFF_OF(B) * 256]);
    } else if constexpr (B < 31) {
        dispatch_k1<B + 1>(b, cw, xs1, ws, otile, ihalf, tid);
    }
}

template<int B>
__device__ __forceinline__ void dispatch_k2(
    int b, const float* __restrict__ cw, const float* __restrict__ xs1,
    float* __restrict__ ws, int otile, int ihalf, int tid)
{
    if (b == B) {
        conv_branch<B - 15, 32 - B, 16>(cw + (size_t)B * (256 * 256 * 32),
                                        xs1, ws, otile, ihalf, tid,
                                        &g_ypart[2 + ihalf][TOFF_OF(B) * 256]);
    } else if constexpr (B < 31) {
        dispatch_k2<B + 1>(b, cw, xs1, ws, otile, ihalf, tid);
    }
}

// ---------------------------------------------------------------------------
// m-partial role (input-only): blocks 0..NQB-1 of the conv grid.
// ---------------------------------------------------------------------------
__device__ void m_role(
    const float* __restrict__ opw, const float* __restrict__ ipw,
    const float* __restrict__ ipb, int blk, int tid, float* __restrict__ a_sh)
{
    const int q0 = blk * QPB;
    float (*a_s)[QPB] = reinterpret_cast<float (*)[QPB]>(a_sh);

    if (tid < 4 * QPB) {
        int w = tid / QPB, qq = tid - w * QPB;
        float a = 0.0f;
        const float* base = opw + (size_t)(128 * w) * TT + (q0 + qq);
#pragma unroll
        for (int j = 0; j < 32; j++) a += base[(size_t)j * TT];
        a_s[w][qq] = a;
    }
    __syncthreads();

    const int t1 = tid, t2 = tid + 256, t3 = tid + 512;
    float acc[4][3] = {};
    for (int qq = 0; qq < QPB; qq++) {
        const float* row = ipw + (size_t)(2 * TT + q0 + qq) * TT;
        float v1 = row[t1];
        float v2 = row[t2];
        float v3 = (t3 < TT) ? row[t3] : 0.0f;
#pragma unroll
        for (int w = 0; w < 4; w++) {
            float aw = a_s[w][qq];
            acc[w][0] = fmaf(aw, v1, acc[w][0]);
            acc[w][1] = fmaf(aw, v2, acc[w][1]);
            acc[w][2] = fmaf(aw, v3, acc[w][2]);
        }
    }
#pragma unroll
    for (int w = 0; w < 4; w++) {
        g_mpart[blk][w][t1] = acc[w][0];
        g_mpart[blk][w][t2] = acc[w][1];
        if (t3 < TT) g_mpart[blk][w][t3] = acc[w][2];
    }
    if (tid < 4) {
        const int w = tid;
        float d = 0.0f;
        for (int qq = 0; qq < QPB; qq++)
            d += a_s[w][qq] * ipb[2 * TT + q0 + qq];
        g_ipbdot[blk][w] = d;
    }
}

__global__ void __launch_bounds__(256, 3) k_conv(
    const float* __restrict__ x, const float* __restrict__ cw,
    const float* __restrict__ opw, const float* __restrict__ ipw,
    const float* __restrict__ ipb)
{
    extern __shared__ float smem[];
    const int tid = threadIdx.x;

    if (blockIdx.x < NQB) {
        m_role(opw, ipw, ipb, blockIdx.x, tid, smem);
        return;
    }

    float* xs1 = smem;
    float* ws  = smem + XS1_FLOATS;

    const int cb = blockIdx.x - NQB;     // 0..767
    const int unit = cb >> 4;            // 0..47
    const int sub = cb & 15;
    const int otile = sub >> 1;
    const int ihalf = sub & 1;

    // transpose-stage x: xs1[il][j] = x(j, ihalf*128 + il)
    for (int idx = tid; idx < 4096; idx += 256) {
        int j = idx >> 7;
        int il = idx & 127;
        xs1[il * XR + j] = x[j * 256 + ihalf * 128 + il];
    }
    __syncthreads();

    // L2-adjacency schedule: unit triplet i -> k1(16+i), k2(16+i), full(15-i).
    const int i = unit / 3;
    const int r = unit - 3 * i;
    if (r == 0)      dispatch_k1<16>(16 + i, cw, xs1, ws, otile, ihalf, tid);
    else if (r == 1) dispatch_k2<16>(16 + i, cw, xs1, ws, otile, ihalf, tid);
    else             dispatch_full<0>(15 - i, cw, xs1, ws, otile, ihalf, tid);
}

// ---------------------------------------------------------------------------
// kA: per (branch, o-group of 32) partial gelu stats {s, s2}.
// ---------------------------------------------------------------------------
__global__ void __launch_bounds__(256) kA(const float* __restrict__ conv_b)
{
    const int b = blockIdx.x >> 3;
    const int og = blockIdx.x & 7;
    const int tid = threadIdx.x;
    const int tg = tid >> 5, lane = tid & 31;
    const int o = og * 32 + lane;
    const int L = 32 - b;
    const int toff = TOFF_OF(b);
    const bool four = (b >= 16);
    const float cbv = conv_b[b * 256 + o];

    float s = 0.0f, s2 = 0.0f;
#pragma unroll
    for (int k = 0; k < 4; k++) {
        int t = tg * 4 + k;
        if (t < L) {
            int idx = (toff + t) * 256 + o;
            float val = g_ypart[0][idx] + g_ypart[1][idx] + cbv;
            if (four) val += g_ypart[2][idx] + g_ypart[3][idx];
            float ge = 0.5f * val * (1.0f + erff(val * 0.70710678118654752440f));
            s += ge;
            s2 += ge * ge;
        }
    }
#pragma unroll
    for (int m = 16; m > 0; m >>= 1) {
        s  += __shfl_xor_sync(0xffffffffu, s, m);
        s2 += __shfl_xor_sync(0xffffffffu, s2, m);
    }
    __shared__ float shs[8], shs2[8];
    if (lane == 0) { shs[tg] = s; shs2[tg] = s2; }
    __syncthreads();
    if (tid == 0) {
        float a = 0.0f, a2 = 0.0f;
#pragma unroll
        for (int j = 0; j < 8; j++) { a += shs[j]; a2 += shs2[j]; }
        g_sp[b][og][0] = a;
        g_sp[b][og][1] = a2;
    }
}

// ---------------------------------------------------------------------------
// kB: 128 blocks (b x tg of 8 t) x 256 threads (o).
// ---------------------------------------------------------------------------
__global__ void __launch_bounds__(256) kB(
    const float* __restrict__ conv_b,
    const float* __restrict__ lnw, const float* __restrict__ lnb,
    const float* __restrict__ opb, float* __restrict__ out)
{
    const int b = blockIdx.x >> 2;
    const int tg = blockIdx.x & 3;
    const int tid = threadIdx.x;
    const int warpIdx = tid >> 5, lane = tid & 31;
    const int o = tid;
    const int L = 32 - b;
    const int toff = TOFF_OF(b);
    const bool four = (b >= 16);

    float a = 0.0f, a2 = 0.0f;
#pragma unroll
    for (int j = 0; j < 8; j++) { a += g_sp[b][j][0]; a2 += g_sp[b][j][1]; }
    const float inv = 1.0f / (float)(256 * L);
    const float mu = a * inv;
    const float rs = rsqrtf(a2 * inv - mu * mu + 1e-5f);

    const float cbv = conv_b[b * 256 + o];
    const float* lwp = lnw + ((size_t)b * 256 + o) * 32;
    const float* lbp = lnb + ((size_t)b * 256 + o) * 32;

    __shared__ float red[8][9];
#pragma unroll
    for (int k = 0; k < 8; k++) {
        int t = tg * 8 + k;
        float c = 0.0f;
        if (t < L) {
            int idx = (toff + t) * 256 + o;
            float val = g_ypart[0][idx] + g_ypart[1][idx] + cbv;
            if (four) val += g_ypart[2][idx] + g_ypart[3][idx];
            float ge = 0.5f * val * (1.0f + erff(val * 0.70710678118654752440f));
            c = fmaf((ge - mu) * rs, lwp[t], lbp[t]);
        }
#pragma unroll
        for (int m = 16; m > 0; m >>= 1) c += __shfl_xor_sync(0xffffffffu, c, m);
        if (lane == 0) red[k][warpIdx] = c;
    }
    __syncthreads();

    if (warpIdx < 4) {
        const int w = warpIdx;
        float pd = 0.0f;
        if (lane < 8) {
            int t = tg * 8 + lane;
            if (t < L) {
                float u = 0.0f;
#pragma unroll
                for (int j = 0; j < 8; j++) u += red[lane][j];
                float m = 0.0f;
#pragma unroll
                for (int blk = 0; blk < NQB; blk++) m += g_mpart[blk][w][toff + t];
                pd = u * m;
            }
        }
#pragma unroll
        for (int mm = 16; mm > 0; mm >>= 1) pd += __shfl_xor_sync(0xffffffffu, pd, mm);
        if (lane == 0) g_pdot2[b * 4 + tg][w] = pd;
    }
    __threadfence();
    __syncthreads();

    __shared__ int s_last;
    if (tid == 0) s_last = (atomicAdd(&g_cnt, 1) == 127) ? 1 : 0;
    __syncthreads();
    if (s_last == 0) return;
    __threadfence();

    __shared__ float tot[4];
    {
        const int w = tid >> 6;
        const int l = tid & 63;
        float v = g_pdot2[l][w] + g_pdot2[l + 64][w];
        if (l < NQB) v += 256.0f * g_ipbdot[l][w];
        if (l < 32) v += 256.0f * opb[128 * w + l];
#pragma unroll
        for (int m = 16; m > 0; m >>= 1) v += __shfl_xor_sync(0xffffffffu, v, m);
        __shared__ float part[8];
        if ((tid & 31) == 0) part[tid >> 5] = v;
        __syncthreads();
        if (tid < 4) tot[tid] = (part[2 * tid] + part[2 * tid + 1]) * (1.0f / 32.0f);
    }
    __syncthreads();
    for (int idx = tid; idx < 1024; idx += 256) out[idx] = tot[idx >> 8];
    if (tid == 0) g_cnt = 0;
}

// ---------------------------------------------------------------------------
extern "C" void kernel_launch(void* const* d_in, const int* in_sizes, int n_in,
                              void* d_out, int out_size)
{
    const float* x      = (const float*)d_in[0];
    const float* conv_w = (const float*)d_in[1];
    const float* conv_b = (const float*)d_in[2];
    const float* ln_w   = (const float*)d_in[3];
    const float* ln_b   = (const float*)d_in[4];
    const float* ipw    = (const float*)d_in[5];
    const float* ipb    = (const float*)d_in[6];
    const float* opw    = (const float*)d_in[7];
    const float* opb    = (const float*)d_in[8];
    float* out = (float*)d_out;

    cudaFuncSetAttribute(k_conv, cudaFuncAttributeMaxDynamicSharedMemorySize,
                         SMEM_BYTES);

    k_conv<<<768 + NQB, 256, SMEM_BYTES>>>(x, conv_w, opw, ipw, ipb);
    kA   <<<256, 256>>>(conv_b);
    kB   <<<128, 256>>>(conv_b, ln_w, ln_b, opb, out);

    (void)in_sizes; (void)n_in; (void)out_size;
}

// round 15
// speedup vs baseline: 1.0578x; 1.0578x over previous
#include <cuda_runtime.h>
#include <math.h>
#include <stddef.h>
#include <stdint.h>

// Problem constants: Dur=32, Dim=256, T=528
#define TT 528
#define NQB 24          // q-partial blocks for m (22 q each)
#define QPB 22

// Scratch (device globals: allocation-free)
// parts: chunk ck (taps [12ck,12ck+12)) x ihalf -> part = 2*ck + ihalf
__device__ float g_ypart[6][256 * TT];
__device__ float g_mpart[NQB][4][TT];
__device__ float g_ipbdot[NQB][4];
__device__ float g_sp[32][8][2];        // per (branch, o-group) partial {s, s2}
__device__ float g_pdot2[128][4];       // per (branch*4+tg, w) partial u.m dot
__device__ int   g_cnt;                 // kB completion counter (self-reset)

// k_conv shared: xs1/xs2 transposed x copies + NBUF weight buffers
#define XR 34
#define XS1_FLOATS (128 * XR)
#define XS_TOTAL (2 * XS1_FLOATS)       // 8704 floats = 34816 B
#define WS_BYTES 36864                  // max: 3 x 256 x 12 x 4
#define SMEM_BYTES (XS_TOTAL * 4 + WS_BYTES)   // 71680 B -> 3 blocks/SM

typedef unsigned long long ull;

__device__ __forceinline__ uint32_t smem_u32(const void* p) {
    return (uint32_t)__cvta_generic_to_shared(p);
}
__device__ __forceinline__ ull pk2(float lo, float hi) {
    ull r;
    asm("mov.b64 %0, {%1, %2};" : "=l"(r) : "f"(lo), "f"(hi));
    return r;
}
__device__ __forceinline__ void upk2(float& lo, float& hi, ull v) {
    asm("mov.b64 {%0, %1}, %2;" : "=f"(lo), "=f"(hi) : "l"(v));
}
__device__ __forceinline__ void fma2(ull& d, ull a, ull b) {
    asm("fma.rn.f32x2 %0, %1, %2, %0;" : "+l"(d) : "l"(a), "l"(b));
}

// ---------------------------------------------------------------------------
// Conv chunk: taps [KOFF, KOFF+K) of a branch with output length L. K <= 12.
// R12 inner loop (dual x copies, inline LDS.64 operands); weight pipeline
// NBUF deep (3 for C4>=2, 8 for C4==1) with conflict-free row strides.
// ---------------------------------------------------------------------------
template<int K, int L, int KOFF>
__device__ __forceinline__ void conv_branch(
    const float* __restrict__ wB,
    const float* __restrict__ xs1, const float* __restrict__ xs2,
    float* __restrict__ ws,
    int otile, int ihalf, int tid,
    float* __restrict__ yout)
{
    constexpr int C4 = (K + 3) / 4;                 // 1..3
    constexpr int SP = (C4 == 1) ? 4 : 12;          // conflict-free strides
    constexpr int NBUF = (C4 == 1) ? 8 : 3;
    constexpr int BUF = 256 * SP;
    constexpr int L2 = L / 2;

    const int g = tid & 7;
    const int o = otile * 32 + (tid >> 3);

    ull acc2[L2 > 0 ? L2 : 1];
#pragma unroll
    for (int t = 0; t < L2; t++) acc2[t] = 0ull;
    float accT = 0.0f;

    auto stage = [&](int ii) {
        const int ibase = ihalf * 128 + ii * 8;
        const uint32_t wsb = smem_u32(ws + (ii % NBUF) * BUF);
#pragma unroll
        for (int k = 0; k < C4; k++) {
            int idx = tid + 256 * k;
            int r = idx / C4;
            int c = idx - r * C4;
            const float* src = wB + (size_t)(otile * 32 + (r >> 3)) * 8192
                                  + (size_t)(ibase + (r & 7)) * 32 + KOFF + c * 4;
            asm volatile("cp.async.cg.shared.global [%0], [%1], 16;"
                         :: "r"(wsb + (uint32_t)(r * SP + c * 4) * 4), "l"(src));
        }
        asm volatile("cp.async.commit_group;");
    };

#pragma unroll
    for (int p = 0; p < NBUF - 1; p++) stage(p);

    for (int ii = 0; ii < 16; ++ii) {
        if (ii <= 16 - NBUF + 1) {
            asm volatile("cp.async.wait_group %0;" :: "n"(NBUF - 2));
        } else {
            asm volatile("cp.async.wait_group 0;");
        }
        __syncthreads();
        if (ii + NBUF - 1 < 16) stage(ii + NBUF - 1);

        const int il = ii * 8 + g;
        const float* x1r = xs1 + il * XR + KOFF;   // KOFF even -> 8B aligned
        const float* x2r = xs2 + il * XR + KOFF;

        // weight row (private, conflict-free) -> packed {w,w} pairs
        const float* wrow = ws + (ii % NBUF) * BUF + tid * SP;
        float wv[C4 * 4];
#pragma unroll
        for (int c = 0; c < C4; c++) {
            float4 w4 = *reinterpret_cast<const float4*>(wrow + c * 4);
            wv[c * 4 + 0] = w4.x; wv[c * 4 + 1] = w4.y;
            wv[c * 4 + 2] = w4.z; wv[c * 4 + 3] = w4.w;
        }
        ull ww[K > 1 ? K : 1];
        if constexpr (L2 > 0) {
#pragma unroll
            for (int h = 0; h < K; h++) ww[h] = pk2(wv[h], wv[h]);
        }

#pragma unroll
        for (int tp = 0; tp < L2; tp++) {
#pragma unroll
            for (int h = 0; h < K; h++) {
                ull xv = (h & 1)
                    ? *reinterpret_cast<const ull*>(x2r + 2 * (tp + (h - 1) / 2))
                    : *reinterpret_cast<const ull*>(x1r + 2 * (tp + h / 2));
                fma2(acc2[tp], xv, ww[h]);
            }
        }
        if constexpr (L & 1) {
#pragma unroll
            for (int h = 0; h < K; h++)
                accT = fmaf(x1r[L - 1 + h], wv[h], accT);
        }
        __syncwarp();
    }

#pragma unroll
    for (int tp = 0; tp < L2; tp++) {
        float a0, a1;
        upk2(a0, a1, acc2[tp]);
#pragma unroll
        for (int m = 1; m <= 4; m <<= 1) {
            a0 += __shfl_xor_sync(0xffffffffu, a0, m);
            a1 += __shfl_xor_sync(0xffffffffu, a1, m);
        }
        if (g == 0) {
            yout[(2 * tp) * 256 + o] = a0;
            yout[(2 * tp + 1) * 256 + o] = a1;
        }
    }
    if constexpr (L & 1) {
#pragma unroll
        for (int m = 1; m <= 4; m <<= 1)
            accT += __shfl_xor_sync(0xffffffffu, accT, m);
        if (g == 0) yout[(L - 1) * 256 + o] = accT;
    }
}

#define TOFF_OF(B) ((B) * 32 - ((B) * ((B) - 1)) / 2)

// ck=0: taps [0,12) (or all of K if K<=12)
template<int B>
__device__ __forceinline__ void dispatch_c0(
    int b, const float* __restrict__ cw,
    const float* __restrict__ xs1, const float* __restrict__ xs2,
    float* __restrict__ ws, int otile, int ihalf, int tid)
{
    if (b == B) {
        constexpr int K0 = (B + 1 <= 12) ? (B + 1) : 12;
        conv_branch<K0, 32 - B, 0>(cw + (size_t)B * (256 * 256 * 32),
                                   xs1, xs2, ws, otile, ihalf, tid,
                                   &g_ypart[ihalf][TOFF_OF(B) * 256]);
    } else if constexpr (B < 31) {
        dispatch_c0<B + 1>(b, cw, xs1, xs2, ws, otile, ihalf, tid);
    }
}

// ck=1: taps [12,24), only b >= 12
template<int B>
__device__ __forceinline__ void dispatch_c1(
    int b, const float* __restrict__ cw,
    const float* __restrict__ xs1, const float* __restrict__ xs2,
    float* __restrict__ ws, int otile, int ihalf, int tid)
{
    if (b == B) {
        constexpr int K1 = (B + 1 - 12 <= 12) ? (B + 1 - 12) : 12;
        conv_branch<K1, 32 - B, 12>(cw + (size_t)B * (256 * 256 * 32),
                                    xs1, xs2, ws, otile, ihalf, tid,
                                    &g_ypart[2 + ihalf][TOFF_OF(B) * 256]);
    } else if constexpr (B < 31) {
        dispatch_c1<B + 1>(b, cw, xs1, xs2, ws, otile, ihalf, tid);
    }
}

// ck=2: taps [24,K), only b >= 24
template<int B>
__device__ __forceinline__ void dispatch_c2(
    int b, const float* __restrict__ cw,
    const float* __restrict__ xs1, const float* __restrict__ xs2,
    float* __restrict__ ws, int otile, int ihalf, int tid)
{
    if (b == B) {
        conv_branch<B + 1 - 24, 32 - B, 24>(cw + (size_t)B * (256 * 256 * 32),
                                            xs1, xs2, ws, otile, ihalf, tid,
                                            &g_ypart[4 + ihalf][TOFF_OF(B) * 256]);
    } else if constexpr (B < 31) {
        dispatch_c2<B + 1>(b, cw, xs1, xs2, ws, otile, ihalf, tid);
    }
}

// ---------------------------------------------------------------------------
// m-partial role (input-only): blocks 0..NQB-1 of the conv grid.
// ---------------------------------------------------------------------------
__device__ void m_role(
    const float* __restrict__ opw, const float* __restrict__ ipw,
    const float* __restrict__ ipb, int blk, int tid, float* __restrict__ a_sh)
{
    const int q0 = blk * QPB;
    float (*a_s)[QPB] = reinterpret_cast<float (*)[QPB]>(a_sh);

    if (tid < 4 * QPB) {
        int w = tid / QPB, qq = tid - w * QPB;
        float a = 0.0f;
        const float* base = opw + (size_t)(128 * w) * TT + (q0 + qq);
#pragma unroll
        for (int j = 0; j < 32; j++) a += base[(size_t)j * TT];
        a_s[w][qq] = a;
    }
    __syncthreads();

    const int t1 = tid, t2 = tid + 256, t3 = tid + 512;
    float acc[4][3] = {};
    for (int qq = 0; qq < QPB; qq++) {
        const float* row = ipw + (size_t)(2 * TT + q0 + qq) * TT;
        float v1 = row[t1];
        float v2 = row[t2];
        float v3 = (t3 < TT) ? row[t3] : 0.0f;
#pragma unroll
        for (int w = 0; w < 4; w++) {
            float aw = a_s[w][qq];
            acc[w][0] = fmaf(aw, v1, acc[w][0]);
            acc[w][1] = fmaf(aw, v2, acc[w][1]);
            acc[w][2] = fmaf(aw, v3, acc[w][2]);
        }
    }
#pragma unroll
    for (int w = 0; w < 4; w++) {
        g_mpart[blk][w][t1] = acc[w][0];
        g_mpart[blk][w][t2] = acc[w][1];
        if (t3 < TT) g_mpart[blk][w][t3] = acc[w][2];
    }
    if (tid < 4) {
        const int w = tid;
        float d = 0.0f;
        for (int qq = 0; qq < QPB; qq++)
            d += a_s[w][qq] * ipb[2 * TT + q0 + qq];
        g_ipbdot[blk][w] = d;
    }
}

__global__ void __launch_bounds__(256, 3) k_conv(
    const float* __restrict__ x, const float* __restrict__ cw,
    const float* __restrict__ opw, const float* __restrict__ ipw,
    const float* __restrict__ ipb)
{
    extern __shared__ float smem[];
    const int tid = threadIdx.x;

    if (blockIdx.x < NQB) {
        m_role(opw, ipw, ipb, blockIdx.x, tid, smem);
        return;
    }

    float* xs1 = smem;
    float* xs2 = smem + XS1_FLOATS;
    float* ws  = smem + XS_TOTAL;

    const int cb = blockIdx.x - NQB;     // 0..959
    const int unit = cb >> 4;            // 0..59
    const int sub = cb & 15;
    const int otile = sub >> 1;
    const int ihalf = sub & 1;

    // transpose-stage x (+1-tau shifted copy)
    for (int idx = tid; idx < 4096; idx += 256) {
        int j = idx >> 7;
        int il = idx & 127;
        float v = x[j * 256 + ihalf * 128 + il];
        xs1[il * XR + j] = v;
        if (j > 0) xs2[il * XR + (j - 1)] = v;
    }
    __syncthreads();

    // Unit schedule: heavy branches first, chunks of one branch ADJACENT
    // (L2 line dedup: all chunks of a branch read the same 128B rows).
    //  u in [0,24):  b = 31 - u/3, ck = u%3
    //  u in [24,48): b = 23 - (u-24)/2, ck = (u-24)%2
    //  u in [48,60): b = 11 - (u-48), ck = 0
    int b, ck;
    if (unit < 24)      { b = 31 - unit / 3; ck = unit % 3; }
    else if (unit < 48) { int v = unit - 24; b = 23 - v / 2; ck = v & 1; }
    else                { b = 11 - (unit - 48); ck = 0; }

    if (ck == 0)      dispatch_c0<0>(b, cw, xs1, xs2, ws, otile, ihalf, tid);
    else if (ck == 1) dispatch_c1<12>(b, cw, xs1, xs2, ws, otile, ihalf, tid);
    else              dispatch_c2<24>(b, cw, xs1, xs2, ws, otile, ihalf, tid);
}

// ---------------------------------------------------------------------------
// kA: per (branch, o-group of 32) partial gelu stats {s, s2}.
// ---------------------------------------------------------------------------
__global__ void __launch_bounds__(256) kA(const float* __restrict__ conv_b)
{
    const int b = blockIdx.x >> 3;
    const int og = blockIdx.x & 7;
    const int tid = threadIdx.x;
    const int tg = tid >> 5, lane = tid & 31;
    const int o = og * 32 + lane;
    const int L = 32 - b;
    const int toff = TOFF_OF(b);
    const float cbv = conv_b[b * 256 + o];

    float s = 0.0f, s2 = 0.0f;
#pragma unroll
    for (int k = 0; k < 4; k++) {
        int t = tg * 4 + k;
        if (t < L) {
            int idx = (toff + t) * 256 + o;
            float val = g_ypart[0][idx] + g_ypart[1][idx] + cbv;
            if (b >= 12) val += g_ypart[2][idx] + g_ypart[3][idx];
            if (b >= 24) val += g_ypart[4][idx] + g_ypart[5][idx];
            float ge = 0.5f * val * (1.0f + erff(val * 0.70710678118654752440f));
            s += ge;
            s2 += ge * ge;
        }
    }
#pragma unroll
    for (int m = 16; m > 0; m >>= 1) {
        s  += __shfl_xor_sync(0xffffffffu, s, m);
        s2 += __shfl_xor_sync(0xffffffffu, s2, m);
    }
    __shared__ float shs[8], shs2[8];
    if (lane == 0) { shs[tg] = s; shs2[tg] = s2; }
    __syncthreads();
    if (tid == 0) {
        float a = 0.0f, a2 = 0.0f;
#pragma unroll
        for (int j = 0; j < 8; j++) { a += shs[j]; a2 += shs2[j]; }
        g_sp[b][og][0] = a;
        g_sp[b][og][1] = a2;
    }
}

// ---------------------------------------------------------------------------
// kB: 128 blocks (b x tg of 8 t) x 256 threads (o).
// ---------------------------------------------------------------------------
__global__ void __launch_bounds__(256) kB(
    const float* __restrict__ conv_b,
    const float* __restrict__ lnw, const float* __restrict__ lnb,
    const float* __restrict__ opb, float* __restrict__ out)
{
    const int b = blockIdx.x >> 2;
    const int tg = blockIdx.x & 3;
    const int tid = threadIdx.x;
    const int warpIdx = tid >> 5, lane = tid & 31;
    const int o = tid;
    const int L = 32 - b;
    const int toff = TOFF_OF(b);

    float a = 0.0f, a2 = 0.0f;
#pragma unroll
    for (int j = 0; j < 8; j++) { a += g_sp[b][j][0]; a2 += g_sp[b][j][1]; }
    const float inv = 1.0f / (float)(256 * L);
    const float mu = a * inv;
    const float rs = rsqrtf(a2 * inv - mu * mu + 1e-5f);

    const float cbv = conv_b[b * 256 + o];
    const float* lwp = lnw + ((size_t)b * 256 + o) * 32;
    const float* lbp = lnb + ((size_t)b * 256 + o) * 32;

    __shared__ float red[8][9];
#pragma unroll
    for (int k = 0; k < 8; k++) {
        int t = tg * 8 + k;
        float c = 0.0f;
        if (t < L) {
            int idx = (toff + t) * 256 + o;
            float val = g_ypart[0][idx] + g_ypart[1][idx] + cbv;
            if (b >= 12) val += g_ypart[2][idx] + g_ypart[3][idx];
            if (b >= 24) val += g_ypart[4][idx] + g_ypart[5][idx];
            float ge = 0.5f * val * (1.0f + erff(val * 0.70710678118654752440f));
            c = fmaf((ge - mu) * rs, lwp[t], lbp[t]);
        }
#pragma unroll
        for (int m = 16; m > 0; m >>= 1) c += __shfl_xor_sync(0xffffffffu, c, m);
        if (lane == 0) red[k][warpIdx] = c;
    }
    __syncthreads();

    if (warpIdx < 4) {
        const int w = warpIdx;
        float pd = 0.0f;
        if (lane < 8) {
            int t = tg * 8 + lane;
            if (t < L) {
                float u = 0.0f;
#pragma unroll
                for (int j = 0; j < 8; j++) u += red[lane][j];
                float m = 0.0f;
#pragma unroll
                for (int blk = 0; blk < NQB; blk++) m += g_mpart[blk][w][toff + t];
                pd = u * m;
            }
        }
#pragma unroll
        for (int mm = 16; mm > 0; mm >>= 1) pd += __shfl_xor_sync(0xffffffffu, pd, mm);
        if (lane == 0) g_pdot2[b * 4 + tg][w] = pd;
    }
    __threadfence();
    __syncthreads();

    __shared__ int s_last;
    if (tid == 0) s_last = (atomicAdd(&g_cnt, 1) == 127) ? 1 : 0;
    __syncthreads();
    if (s_last == 0) return;
    __threadfence();

    __shared__ float tot[4];
    {
        const int w = tid >> 6;
        const int l = tid & 63;
        float v = g_pdot2[l][w] + g_pdot2[l + 64][w];
        if (l < NQB) v += 256.0f * g_ipbdot[l][w];
        if (l < 32) v += 256.0f * opb[128 * w + l];
#pragma unroll
        for (int m = 16; m > 0; m >>= 1) v += __shfl_xor_sync(0xffffffffu, v, m);
        __shared__ float part[8];
        if ((tid & 31) == 0) part[tid >> 5] = v;
        __syncthreads();
        if (tid < 4) tot[tid] = (part[2 * tid] + part[2 * tid + 1]) * (1.0f / 32.0f);
    }
    __syncthreads();
    for (int idx = tid; idx < 1024; idx += 256) out[idx] = tot[idx >> 8];
    if (tid == 0) g_cnt = 0;
}

// ---------------------------------------------------------------------------
extern "C" void kernel_launch(void* const* d_in, const int* in_sizes, int n_in,
                              void* d_out, int out_size)
{
    const float* x      = (const float*)d_in[0];
    const float* conv_w = (const float*)d_in[1];
    const float* conv_b = (const float*)d_in[2];
    const float* ln_w   = (const float*)d_in[3];
    const float* ln_b   = (const float*)d_in[4];
    const float* ipw    = (const float*)d_in[5];
    const float* ipb    = (const float*)d_in[6];
    const float* opw    = (const float*)d_in[7];
    const float* opb    = (const float*)d_in[8];
    float* out = (float*)d_out;

    cudaFuncSetAttribute(k_conv, cudaFuncAttributeMaxDynamicSharedMemorySize,
                         SMEM_BYTES);

    k_conv<<<960 + NQB, 256, SMEM_BYTES>>>(x, conv_w, opw, ipw, ipb);
    kA   <<<256, 256>>>(conv_b);
    kB   <<<128, 256>>>(conv_b, ln_w, ln_b, opb, out);

    (void)in_sizes; (void)n_in; (void)out_size;
}